// round 5
// baseline (speedup 1.0000x reference)
#include <cuda_runtime.h>

// LocallyConnectedLinear: out[b,h,w,o] = sum_k xpatch[b,h,w,k] * W[h,w,k,o]
// x:  [8, 32, 32, 64]  f32   (NHWC)
// W:  [30, 30, 576, 64] f32  (k = c*9 + kh*3 + kw ; C slowest)
// out:[8, 30, 30, 64]  f32
//
// HBM-bound on the 132.7 MB weight stream (floor ~17us @ 8TB/s).
// R1 53.7us: 8x duplicated weight reads (L1-bound).
// R2 31.2us: unique weight reads, scalar FFMA. Issue-mix-bound:
//            36 instr / 512B weights needs ~53% issue; we sustain 36%.
// R3 39.4us: FFMA2 with x duplicated in smem -> 2x LDS traffic. Reverted.
// R4 33.3us: o-split grid + interleaved k. Same issue ceiling.
// R5: FFMA2 pairing accumulators over BATCH: x pairs (b0,b1) are free 64-bit
//     halves of the existing LDS.128; only weights get dup'd ((w,w) via
//     mov.b64, ALU pipe). 16 FFMA2 + 8 MOV per k instead of 32 FFMA.

#define H_OUT 30
#define W_OUT 30
#define H_IN  32
#define W_IN  32
#define C_IN  64
#define C_OUT 64
#define KK    576   // 64 * 3 * 3
#define BATCH 8
#define NTHREADS 128
#define NSLICE 16   // interleaved: slice s owns k == s (mod 16)
#define KPS    36   // KK / NSLICE
#define NO4    8    // float4 output groups per CTA (32 of 64 channels)

typedef unsigned long long u64;

__device__ __forceinline__ u64 fma2(u64 a, u64 b, u64 c) {
    u64 d;
    asm("fma.rn.f32x2 %0, %1, %2, %3;" : "=l"(d) : "l"(a), "l"(b), "l"(c));
    return d;
}
__device__ __forceinline__ u64 add2(u64 a, u64 b) {
    u64 d;
    asm("add.rn.f32x2 %0, %1, %2;" : "=l"(d) : "l"(a), "l"(b));
    return d;
}
__device__ __forceinline__ u64 dupf(float v) {
    u64 d;
    asm("mov.b64 %0, {%1, %1};" : "=l"(d) : "f"(v));
    return d;
}

__global__ __launch_bounds__(NTHREADS, 6)
void lc_kernel(const float* __restrict__ x,
               const float* __restrict__ w,
               float* __restrict__ out)
{
    // Phase 1: xs[k][b], KK x 8 floats = 18432 B.
    // Phase 2 (aliased): red[128 rows][17 u64] = 17408 B.
    __shared__ __align__(16) float smem[KK * BATCH];

    const int bid = blockIdx.x;          // 0..1799
    const int loc = bid >> 1;            // 0..899
    const int oh  = bid & 1;             // channel half: [oh*32, oh*32+32)
    const int h   = loc / W_OUT;
    const int wo  = loc - h * W_OUT;
    const int tid = threadIdx.x;

    // ---- Stage im2col patch: xs[k][b], k = c*9 + kh*3 + kw (c fastest: coalesced) ----
    #pragma unroll
    for (int idx = tid; idx < BATCH * KK; idx += NTHREADS) {
        const int b   = idx / KK;
        const int r   = idx - b * KK;     // r = (kh*3+kw)*64 + c
        const int khw = r >> 6;           // kh*3 + kw
        const int c   = r & 63;
        const int kh  = khw / 3;
        const int kw  = khw - kh * 3;
        const int k   = c * 9 + khw;
        smem[k * BATCH + b] =
            x[(((b * H_IN) + h + kh) * W_IN + (wo + kw)) * C_IN + c];
    }
    __syncthreads();

    // ---- Main loop: thread = (ks, o4); slice ks owns k = ks + 16j.
    // Warp = 4 consecutive ks x 8 o4 -> conflict-free LDS, 4 full lines/LDG.
    const int o4 = tid & (NO4 - 1);   // 0..7
    const int ks = tid >> 3;          // 0..15
    const float4* __restrict__ Wp =
        (const float4*)(w + (size_t)loc * (KK * C_OUT)) + oh * 8 + o4;  // [KK][16]

    // acc[p*4 + o]: p = batch pair (b=2p, 2p+1), o = local float index 0..3
    u64 acc[16];
    #pragma unroll
    for (int i = 0; i < 16; ++i) acc[i] = 0ull;

    #pragma unroll 6
    for (int j = 0; j < KPS; ++j) {
        const int k = ks + j * NSLICE;
        const float4 wv = __ldcs(Wp + k * (C_OUT / 4));  // streaming LDG.128
        const ulonglong2 xa = *(const ulonglong2*)(smem + k * BATCH);     // (b01,b23)
        const ulonglong2 xb = *(const ulonglong2*)(smem + k * BATCH + 4); // (b45,b67)
        const u64 w0 = dupf(wv.x), w1 = dupf(wv.y), w2 = dupf(wv.z), w3 = dupf(wv.w);
        acc[ 0] = fma2(xa.x, w0, acc[ 0]);
        acc[ 1] = fma2(xa.x, w1, acc[ 1]);
        acc[ 2] = fma2(xa.x, w2, acc[ 2]);
        acc[ 3] = fma2(xa.x, w3, acc[ 3]);
        acc[ 4] = fma2(xa.y, w0, acc[ 4]);
        acc[ 5] = fma2(xa.y, w1, acc[ 5]);
        acc[ 6] = fma2(xa.y, w2, acc[ 6]);
        acc[ 7] = fma2(xa.y, w3, acc[ 7]);
        acc[ 8] = fma2(xb.x, w0, acc[ 8]);
        acc[ 9] = fma2(xb.x, w1, acc[ 9]);
        acc[10] = fma2(xb.x, w2, acc[10]);
        acc[11] = fma2(xb.x, w3, acc[11]);
        acc[12] = fma2(xb.y, w0, acc[12]);
        acc[13] = fma2(xb.y, w1, acc[13]);
        acc[14] = fma2(xb.y, w2, acc[14]);
        acc[15] = fma2(xb.y, w3, acc[15]);
    }

    // ---- Reduce 16 k-slices through smem (aliased) ----
    __syncthreads();   // everyone done reading xs
    u64* red = (u64*)smem;             // [128 rows (=tid=ks*8+o4)][17]
    #pragma unroll
    for (int i = 0; i < 16; ++i)
        red[tid * 17 + i] = acc[i];
    __syncthreads();

    // Final: tid = (p<<5) | (o4f<<2) | ol  -> warp-coalesced output stores.
    {
        const int ol  = tid & 3;          // local float in float4 group
        const int o4f = (tid >> 2) & 7;   // float4 group within half
        const int p   = tid >> 5;         // batch pair -> b = 2p, 2p+1
        const int off = p * 4 + ol;

        u64 s = red[o4f * 17 + off];
        #pragma unroll
        for (int sl = 1; sl < NSLICE; ++sl)
            s = add2(s, red[((sl << 3) + o4f) * 17 + off]);

        const float2 fv = *(const float2*)&s;
        const int og = (oh * 8 + o4f) * 4 + ol;           // global channel
        const size_t base = ((size_t)(h * W_OUT + wo)) * C_OUT + og;
        const size_t bstride = (size_t)H_OUT * W_OUT * C_OUT;
        out[(size_t)(2 * p)     * bstride + base] = fv.x;
        out[(size_t)(2 * p + 1) * bstride + base] = fv.y;
    }
}

extern "C" void kernel_launch(void* const* d_in, const int* in_sizes, int n_in,
                              void* d_out, int out_size)
{
    const float* x  = (const float*)d_in[0];   // [8,32,32,64]
    const float* w  = (const float*)d_in[1];   // [30,30,576,64]
    float*       o  = (float*)d_out;           // [8,30,30,64]
    (void)in_sizes; (void)n_in; (void)out_size;

    lc_kernel<<<H_OUT * W_OUT * 2, NTHREADS>>>(x, w, o);
}